// round 1
// baseline (speedup 1.0000x reference)
#include <cuda_runtime.h>
#include <cstdint>
#include <cstddef>

#define NFFT 8192
#define LOGN 13
#define NTOK 4096
#define DDIM 1024
#define FDIM 4096
#define NBATCH 4

// ---------------- scratch (device globals; no allocation allowed) ----------------
__device__ float g_twre[NFFT / 2];
__device__ float g_twim[NFFT / 2];
__device__ float g_wfre[NFFT];
__device__ float g_wfim[NFFT];
__device__ float g_x1[(size_t)NBATCH * NTOK * DDIM];          // 64 MB: residual -> x1 (post-LN, in place)
__device__ float g_H[(size_t)NBATCH * NTOK * FDIM];           // 256 MB: hidden activations
__device__ float g_V[(size_t)NBATCH * NTOK * DDIM];           // 64 MB: second-GEMM output

// ---------------- FFT helpers (in shared memory, SoA) ----------------
// Forward DIF: natural-order input, bit-reversed output. Twiddle W[k]=exp(-2pi i k/8192).
__device__ __forceinline__ void fft_fwd(float* re, float* im,
                                        const float* twre, const float* twim) {
    for (int s = 0; s < LOGN; s++) {
        const int hs = (LOGN - 1) - s;
        const int half = 1 << hs;
        for (int t = threadIdx.x; t < NFFT / 2; t += blockDim.x) {
            const int p = t & (half - 1);
            const int i0 = ((t >> hs) << (hs + 1)) | p;
            const int i1 = i0 + half;
            const int k = p << s;
            const float wr = twre[k], wi = twim[k];
            const float ar = re[i0], ai = im[i0];
            const float br = re[i1], bi = im[i1];
            re[i0] = ar + br;
            im[i0] = ai + bi;
            const float tr = ar - br, ti = ai - bi;
            re[i1] = tr * wr - ti * wi;
            im[i1] = tr * wi + ti * wr;
        }
        __syncthreads();
    }
}

// Inverse DIT: bit-reversed input, natural output, conjugate twiddles, unnormalized.
__device__ __forceinline__ void fft_inv(float* re, float* im,
                                        const float* twre, const float* twim) {
    for (int s = 0; s < LOGN; s++) {
        const int hs = s;
        const int half = 1 << s;
        for (int t = threadIdx.x; t < NFFT / 2; t += blockDim.x) {
            const int p = t & (half - 1);
            const int i0 = ((t >> hs) << (hs + 1)) | p;
            const int i1 = i0 + half;
            const int k = p << ((LOGN - 1) - s);
            const float wr = twre[k], wi = -twim[k];   // conj
            const float br = re[i1], bi = im[i1];
            const float cr = br * wr - bi * wi;
            const float ci = br * wi + bi * wr;
            const float ar = re[i0], ai = im[i0];
            re[i0] = ar + cr;
            im[i0] = ai + ci;
            re[i1] = ar - cr;
            im[i1] = ai - ci;
        }
        __syncthreads();
    }
}

// ---------------- kernel 1: twiddle table + WF = DIF(w zero-padded), bit-reversed ----------------
extern __shared__ float smem_f[];

__global__ void wf_kernel(const float* __restrict__ w) {
    float* re = smem_f;
    float* im = smem_f + NFFT;
    float* twre = smem_f + 2 * NFFT;
    float* twim = twre + NFFT / 2;

    const float ang0 = -6.283185307179586476f / (float)NFFT;
    for (int k = threadIdx.x; k < NFFT / 2; k += blockDim.x) {
        float sv, cv;
        sincosf(ang0 * (float)k, &sv, &cv);
        twre[k] = cv; twim[k] = sv;
        g_twre[k] = cv; g_twim[k] = sv;
    }
    for (int n = threadIdx.x; n < NFFT; n += blockDim.x) {
        re[n] = (n < NTOK) ? w[n] : 0.0f;
        im[n] = 0.0f;
    }
    __syncthreads();
    fft_fwd(re, im, twre, twim);
    for (int j = threadIdx.x; j < NFFT; j += blockDim.x) {
        g_wfre[j] = re[j];
        g_wfim[j] = im[j];
    }
}

// ---------------- kernel 2: per 2-channel FFT conv + residual ----------------
// CTA c handles channels (b, da) and (b, da+1), packed as re/im of one complex FFT.
// Writes r = x + y*sqrt(1/(n+1)) into g_x1.
__global__ void conv_kernel(const float* __restrict__ x) {
    float* re = smem_f;
    float* im = smem_f + NFFT;
    float* twre = smem_f + 2 * NFFT;
    float* twim = twre + NFFT / 2;

    const int b = blockIdx.x >> 9;            // D/2 = 512 pairs per batch
    const int da = (blockIdx.x & 511) << 1;
    const float* xp = x + (size_t)b * NTOK * DDIM + da;

    for (int k = threadIdx.x; k < NFFT / 2; k += blockDim.x) {
        twre[k] = g_twre[k];
        twim[k] = g_twim[k];
    }
    for (int n = threadIdx.x; n < NTOK; n += blockDim.x) {
        const float2 v = *(const float2*)(xp + (size_t)n * DDIM);
        re[n] = v.x;
        im[n] = v.y;
    }
    for (int n = NTOK + threadIdx.x; n < NFFT; n += blockDim.x) {
        re[n] = 0.0f;
        im[n] = 0.0f;
    }
    __syncthreads();

    fft_fwd(re, im, twre, twim);

    // pointwise multiply in bit-reversed frequency domain (coalesced global reads)
    for (int j = threadIdx.x; j < NFFT; j += blockDim.x) {
        const float zr = re[j], zi = im[j];
        const float wr = g_wfre[j], wi = g_wfim[j];
        re[j] = zr * wr - zi * wi;
        im[j] = zr * wi + zi * wr;
    }
    __syncthreads();

    fft_inv(re, im, twre, twim);

    float* rp = g_x1 + (size_t)b * NTOK * DDIM + da;
    const float invN = 1.0f / (float)NFFT;
    for (int n = threadIdx.x; n < NTOK; n += blockDim.x) {
        const float2 v = *(const float2*)(xp + (size_t)n * DDIM);
        const float sc = rsqrtf((float)(n + 1)) * invN;
        float2 o;
        o.x = v.x + re[n] * sc;
        o.y = v.y + im[n] * sc;
        *(float2*)(rp + (size_t)n * DDIM) = o;
    }
}

// ---------------- block reduce (sum, sumsq) over 256 threads ----------------
__device__ __forceinline__ void blockReduce2(float& s1, float& s2) {
    __shared__ float r1[8], r2[8];
    const int lane = threadIdx.x & 31;
    const int warp = threadIdx.x >> 5;
#pragma unroll
    for (int o = 16; o; o >>= 1) {
        s1 += __shfl_xor_sync(0xffffffffu, s1, o);
        s2 += __shfl_xor_sync(0xffffffffu, s2, o);
    }
    if (lane == 0) { r1[warp] = s1; r2[warp] = s2; }
    __syncthreads();
    if (warp == 0) {
        s1 = (lane < 8) ? r1[lane] : 0.0f;
        s2 = (lane < 8) ? r2[lane] : 0.0f;
#pragma unroll
        for (int o = 4; o; o >>= 1) {
            s1 += __shfl_xor_sync(0xffffffffu, s1, o);
            s2 += __shfl_xor_sync(0xffffffffu, s2, o);
        }
        if (lane == 0) { r1[0] = s1; r2[0] = s2; }
    }
    __syncthreads();
    s1 = r1[0];
    s2 = r2[0];
}

// ---------------- kernel 3: LayerNorm in place on g_x1 ----------------
__global__ void ln1_kernel(const float* __restrict__ g, const float* __restrict__ bb) {
    float* row = g_x1 + (size_t)blockIdx.x * DDIM;
    const int t = threadIdx.x;
    const float4 v = ((const float4*)row)[t];
    float s1 = v.x + v.y + v.z + v.w;
    float s2 = v.x * v.x + v.y * v.y + v.z * v.z + v.w * v.w;
    blockReduce2(s1, s2);
    const float mu = s1 * (1.0f / DDIM);
    const float var = fmaxf(s2 * (1.0f / DDIM) - mu * mu, 0.0f);
    const float rstd = rsqrtf(var + 1e-5f);
    const float4 gg = ((const float4*)g)[t];
    const float4 bv = ((const float4*)bb)[t];
    float4 o;
    o.x = (v.x - mu) * rstd * gg.x + bv.x;
    o.y = (v.y - mu) * rstd * gg.y + bv.y;
    o.z = (v.z - mu) * rstd * gg.z + bv.z;
    o.w = (v.w - mu) * rstd * gg.w + bv.w;
    ((float4*)row)[t] = o;
}

// ---------------- kernel 4/5: tiled SGEMM  C = A * B^T (+bias, opt GELU) ----------------
// mode 0: A = g_x1 expert/batch block [2048 x 1024], B = w1_e [4096 x 1024], C = g_H, gelu
// mode 1: A = g_H block [2048 x 4096],              B = w2_e [1024 x 4096], C = g_V
__global__ __launch_bounds__(256, 2)
void sgemm_kernel(int mode,
                  const float* __restrict__ Bw0, const float* __restrict__ Bw1,
                  const float* __restrict__ bias0, const float* __restrict__ bias1,
                  int K, int N) {
    constexpr int BM = 128, BN = 128, BK = 8;
    __shared__ __align__(16) float As[BK][BM];
    __shared__ __align__(16) float Bs[BK][BN];

    const int z = blockIdx.z;          // z = e*4 + b
    const int e = z >> 2;
    const int b = z & 3;

    const float* A;
    float* C;
    if (mode == 0) {
        A = g_x1 + ((size_t)b * NTOK + (size_t)e * 2048) * DDIM;
        C = g_H + (size_t)z * 2048 * FDIM;
    } else {
        A = g_H + (size_t)z * 2048 * FDIM;
        C = g_V + (size_t)z * 2048 * DDIM;
    }
    A += (size_t)blockIdx.y * BM * K;
    const float* Bw = (e ? Bw1 : Bw0) + (size_t)blockIdx.x * BN * K;
    const float* bias = e ? bias1 : bias0;

    const int tid = threadIdx.x;
    const int tCol = tid & 15;          // 16 cols of threads
    const int tRow = tid >> 4;          // 16 rows of threads
    const int ldRow = tid >> 1;         // 128 rows, 2 float4/row along K
    const int ldCol = (tid & 1) << 2;

    float acc[8][8];
#pragma unroll
    for (int i = 0; i < 8; i++)
#pragma unroll
        for (int j = 0; j < 8; j++) acc[i][j] = 0.0f;

    for (int k0 = 0; k0 < K; k0 += BK) {
        const float4 ta = *(const float4*)(A + (size_t)ldRow * K + k0 + ldCol);
        const float4 tb = *(const float4*)(Bw + (size_t)ldRow * K + k0 + ldCol);
        As[ldCol + 0][ldRow] = ta.x;
        As[ldCol + 1][ldRow] = ta.y;
        As[ldCol + 2][ldRow] = ta.z;
        As[ldCol + 3][ldRow] = ta.w;
        Bs[ldCol + 0][ldRow] = tb.x;
        Bs[ldCol + 1][ldRow] = tb.y;
        Bs[ldCol + 2][ldRow] = tb.z;
        Bs[ldCol + 3][ldRow] = tb.w;
        __syncthreads();
#pragma unroll
        for (int k = 0; k < BK; k++) {
            float rm[8], rn[8];
            *(float4*)&rm[0] = *(const float4*)&As[k][tRow * 8];
            *(float4*)&rm[4] = *(const float4*)&As[k][tRow * 8 + 4];
            *(float4*)&rn[0] = *(const float4*)&Bs[k][tCol * 8];
            *(float4*)&rn[4] = *(const float4*)&Bs[k][tCol * 8 + 4];
#pragma unroll
            for (int i = 0; i < 8; i++)
#pragma unroll
                for (int j = 0; j < 8; j++) acc[i][j] += rm[i] * rn[j];
        }
        __syncthreads();
    }

    const int row0 = blockIdx.y * BM + tRow * 8;
    const int col0 = blockIdx.x * BN + tCol * 8;
    float bv[8];
#pragma unroll
    for (int j = 0; j < 8; j++) bv[j] = bias[col0 + j];

#pragma unroll
    for (int i = 0; i < 8; i++) {
        float vals[8];
#pragma unroll
        for (int j = 0; j < 8; j++) {
            float v = acc[i][j] + bv[j];
            if (mode == 0) v = 0.5f * v * (1.0f + erff(v * 0.70710678118654752f));
            vals[j] = v;
        }
        float* cr = C + (size_t)(row0 + i) * N + col0;
        *(float4*)cr = *(const float4*)&vals[0];
        *(float4*)(cr + 4) = *(const float4*)&vals[4];
    }
}

// ---------------- kernel 6: residual + scalar + LayerNorm -> out ----------------
__global__ void final_kernel(const float* __restrict__ lng0, const float* __restrict__ lnb0,
                             const float* __restrict__ lng1, const float* __restrict__ lnb1,
                             const float* __restrict__ s0, const float* __restrict__ s1p,
                             float* __restrict__ out) {
    const int gRow = blockIdx.x;             // 0..16383 = b*4096 + n
    const int b = gRow >> 12;
    const int n = gRow & 4095;
    const int e = n >> 11;
    const int z = e * 4 + b;
    const float* vrow = g_V + ((size_t)z * 2048 + (size_t)(n & 2047)) * DDIM;
    const float* xrow = g_x1 + (size_t)gRow * DDIM;
    const float sc = e ? s1p[0] : s0[0];
    const float* g = e ? lng1 : lng0;
    const float* bb = e ? lnb1 : lnb0;

    const int t = threadIdx.x;
    const float4 xv = ((const float4*)xrow)[t];
    const float4 vv = ((const float4*)vrow)[t];
    float4 w;
    w.x = xv.x + vv.x * sc;
    w.y = xv.y + vv.y * sc;
    w.z = xv.z + vv.z * sc;
    w.w = xv.w + vv.w * sc;
    float s1 = w.x + w.y + w.z + w.w;
    float s2 = w.x * w.x + w.y * w.y + w.z * w.z + w.w * w.w;
    blockReduce2(s1, s2);
    const float mu = s1 * (1.0f / DDIM);
    const float var = fmaxf(s2 * (1.0f / DDIM) - mu * mu, 0.0f);
    const float rstd = rsqrtf(var + 1e-5f);
    const float4 gg = ((const float4*)g)[t];
    const float4 bv = ((const float4*)bb)[t];
    float4 o;
    o.x = (w.x - mu) * rstd * gg.x + bv.x;
    o.y = (w.y - mu) * rstd * gg.y + bv.y;
    o.z = (w.z - mu) * rstd * gg.z + bv.z;
    o.w = (w.w - mu) * rstd * gg.w + bv.w;
    ((float4*)(out + (size_t)gRow * DDIM))[t] = o;
}

// ---------------- launch ----------------
extern "C" void kernel_launch(void* const* d_in, const int* in_sizes, int n_in,
                              void* d_out, int out_size) {
    const float* x     = (const float*)d_in[0];
    const float* wts   = (const float*)d_in[1];
    const float* ng    = (const float*)d_in[2];
    const float* nb    = (const float*)d_in[3];
    const float* w1_0  = (const float*)d_in[4];
    const float* b1_0  = (const float*)d_in[5];
    const float* w2_0  = (const float*)d_in[6];
    const float* b2_0  = (const float*)d_in[7];
    const float* s_0   = (const float*)d_in[8];
    const float* lng_0 = (const float*)d_in[9];
    const float* lnb_0 = (const float*)d_in[10];
    const float* w1_1  = (const float*)d_in[11];
    const float* b1_1  = (const float*)d_in[12];
    const float* w2_1  = (const float*)d_in[13];
    const float* b2_1  = (const float*)d_in[14];
    const float* s_1   = (const float*)d_in[15];
    const float* lng_1 = (const float*)d_in[16];
    const float* lnb_1 = (const float*)d_in[17];
    float* out = (float*)d_out;

    const int SMEMB = (2 * NFFT + NFFT) * (int)sizeof(float);   // re+im+twiddles = 96 KB
    cudaFuncSetAttribute(wf_kernel, cudaFuncAttributeMaxDynamicSharedMemorySize, SMEMB);
    cudaFuncSetAttribute(conv_kernel, cudaFuncAttributeMaxDynamicSharedMemorySize, SMEMB);

    // 1) spectrum of kernel (bit-reversed) + master twiddle table
    wf_kernel<<<1, 512, SMEMB>>>(wts);
    // 2) FFT conv (2 channels/CTA) + residual scale -> g_x1
    conv_kernel<<<2048, 512, SMEMB>>>(x);
    // 3) LayerNorm in place
    ln1_kernel<<<NBATCH * NTOK, 256>>>(ng, nb);
    // 4) H = gelu(x1 @ W1^T + b1)
    dim3 g1(FDIM / 128, 2048 / 128, 8);
    sgemm_kernel<<<g1, 256>>>(0, w1_0, w1_1, b1_0, b1_1, DDIM, FDIM);
    // 5) V = H @ W2^T + b2
    dim3 g2(DDIM / 128, 2048 / 128, 8);
    sgemm_kernel<<<g2, 256>>>(1, w2_0, w2_1, b2_0, b2_1, FDIM, DDIM);
    // 6) out = LN(x1 + V*s)
    final_kernel<<<NBATCH * NTOK, 256>>>(lng_0, lnb_0, lng_1, lnb_1, s_0, s_1, out);
}